// round 17
// baseline (speedup 1.0000x reference)
#include <cuda_runtime.h>
#include <cuda_fp16.h>
#include <cstdint>

#define N_NODES 100000
#define N_EDGES 1600000
#define IN_C 128
#define OUT_C 128
#define CAP 128                     // bucket capacity per node (deg ~ Poisson(32))

// GEMM tiling: each GEMM-role block processes 2 M=64 tiles
#define GEMM_M_TILE 64
#define GEMM_TILES ((N_NODES + GEMM_M_TILE - 1) / GEMM_M_TILE)  // 1563
#define TILES_PER_BLOCK 2
#define GEMM_BLOCKS ((GEMM_TILES + TILES_PER_BLOCK - 1) / TILES_PER_BLOCK)  // 782

#define FILL_EPT 2
#define FILL_THREADS 256
#define FILL_BLOCKS (N_EDGES / (FILL_THREADS * FILL_EPT))       // 3125 exact
#define FUSED_BLOCKS (GEMM_BLOCKS + FILL_BLOCKS)                // 3907

#define WT_PAD 8
#define WT_LD (IN_C + WT_PAD)   // 136 halves row stride

// ---- scratch in __device__ globals (no cudaMalloc allowed) ----
__device__ __half g_xwh[(size_t)N_NODES * OUT_C]; // 25.6 MB; unscaled, then scaled in-place
__device__ float  g_dinv[N_NODES];
__device__ int    g_cursor[N_NODES];              // memset to 0; fill bumps -> deg
__device__ int    g_col[(size_t)N_NODES * CAP];   // 51.2 MB bucketed adjacency

__device__ __forceinline__ unsigned h2_to_u32(__half2 h) {
    return *reinterpret_cast<unsigned*>(&h);
}

// ------------------------------------------------------------------
// Fused GEMM (unscaled fp16 out, 2 M-tiles per block) + one-pass bucketed fill.
__global__ __launch_bounds__(256, 4) void k_gemm_fill(const float* __restrict__ x,
                                                      const float* __restrict__ W,
                                                      const int* __restrict__ ei) {
    const int bid = blockIdx.x;
    const bool is_gemm = (bid % 5 == 0);

    if (!is_gemm) {
        // ---------------- fill role: one-pass bucket insert ----------------
        const int fill_id = bid - bid / 5 - 1;
        int e = (fill_id * FILL_THREADS + threadIdx.x) * FILL_EPT;
        if (e + 1 < N_EDGES) {
            int a0 = ei[e],     b0 = ei[N_EDGES + e];
            int a1 = ei[e + 1], b1 = ei[N_EDGES + e + 1];
            int p0 = atomicAdd(&g_cursor[a0], 1);
            int p1 = atomicAdd(&g_cursor[b0], 1);
            int p2 = atomicAdd(&g_cursor[a1], 1);
            int p3 = atomicAdd(&g_cursor[b1], 1);
            if (p0 < CAP) g_col[(size_t)a0 * CAP + p0] = b0;
            if (p1 < CAP) g_col[(size_t)b0 * CAP + p1] = a0;
            if (p2 < CAP) g_col[(size_t)a1 * CAP + p2] = b1;
            if (p3 < CAP) g_col[(size_t)b1 * CAP + p3] = a1;
        } else if (e < N_EDGES) {
            int a = ei[e];
            int b = ei[N_EDGES + e];
            int pa = atomicAdd(&g_cursor[a], 1);
            int pb = atomicAdd(&g_cursor[b], 1);
            if (pa < CAP) g_col[(size_t)a * CAP + pa] = b;
            if (pb < CAP) g_col[(size_t)b * CAP + pb] = a;
        }
        return;
    }

    // ---------------- GEMM role: stage W once, run 2 M=64 tiles ----------------
    __shared__ __half wt[OUT_C][WT_LD];   // W^T: wt[n][k]
    const int gemm_blk = bid / 5;
    const int tid  = threadIdx.x;
    const int wid  = tid >> 5;            // 0..7
    const int lane = tid & 31;

    for (int i = tid; i < IN_C * OUT_C; i += 256) {
        int k = i >> 7;
        int n = i & 127;
        wt[n][k] = __float2half(W[(size_t)k * OUT_C + n]);
    }
    __syncthreads();

    const int m_tile  = wid >> 1;          // 0..3
    const int n_half  = (wid & 1) * 64;    // 0 or 64
    const int qr = lane >> 2;
    const int qc = lane & 3;

    #pragma unroll
    for (int t = 0; t < TILES_PER_BLOCK; t++) {
        const int gemm_id = gemm_blk * TILES_PER_BLOCK + t;
        if (gemm_id >= GEMM_TILES) break;

        const int row_base = gemm_id * GEMM_M_TILE + m_tile * 16;
        const int r0 = row_base + qr;
        const int r1 = r0 + 8;
        const int r0c = (r0 < N_NODES) ? r0 : (N_NODES - 1);
        const int r1c = (r1 < N_NODES) ? r1 : (N_NODES - 1);
        const float* xr0 = x + (size_t)r0c * IN_C;
        const float* xr1 = x + (size_t)r1c * IN_C;

        float acc[8][4];
        #pragma unroll
        for (int nt = 0; nt < 8; nt++)
            #pragma unroll
            for (int q = 0; q < 4; q++) acc[nt][q] = 0.0f;

        #pragma unroll
        for (int ks = 0; ks < IN_C / 16; ks++) {
            const int k0 = ks * 16 + qc * 2;
            float2 f;
            f = *(const float2*)(xr0 + k0);     unsigned a0 = h2_to_u32(__float22half2_rn(f));
            f = *(const float2*)(xr1 + k0);     unsigned a1 = h2_to_u32(__float22half2_rn(f));
            f = *(const float2*)(xr0 + k0 + 8); unsigned a2 = h2_to_u32(__float22half2_rn(f));
            f = *(const float2*)(xr1 + k0 + 8); unsigned a3 = h2_to_u32(__float22half2_rn(f));

            #pragma unroll
            for (int nt = 0; nt < 8; nt++) {
                const int n = n_half + nt * 8 + qr;
                unsigned b0 = *(const unsigned*)&wt[n][k0];
                unsigned b1 = *(const unsigned*)&wt[n][k0 + 8];
                asm volatile(
                    "mma.sync.aligned.m16n8k16.row.col.f32.f16.f16.f32 "
                    "{%0,%1,%2,%3}, {%4,%5,%6,%7}, {%8,%9}, {%0,%1,%2,%3};\n"
                    : "+f"(acc[nt][0]), "+f"(acc[nt][1]), "+f"(acc[nt][2]), "+f"(acc[nt][3])
                    : "r"(a0), "r"(a1), "r"(a2), "r"(a3), "r"(b0), "r"(b1));
            }
        }

        #pragma unroll
        for (int nt = 0; nt < 8; nt++) {
            const int n = n_half + nt * 8 + qc * 2;
            if (r0 < N_NODES) {
                __half2 h = __floats2half2_rn(acc[nt][0], acc[nt][1]);
                *(__half2*)(g_xwh + (size_t)r0 * OUT_C + n) = h;
            }
            if (r1 < N_NODES) {
                __half2 h = __floats2half2_rn(acc[nt][2], acc[nt][3]);
                *(__half2*)(g_xwh + (size_t)r1 * OUT_C + n) = h;
            }
        }
    }
}

// ------------------------------------------------------------------
// scale pass: dinv[n] = rsqrt(deg+1); xwh[n] *= dinv[n] in place (fp16 RMW).
__global__ void k_scale() {
    const int gid  = blockIdx.x * blockDim.x + threadIdx.x;
    const int node = gid >> 5;
    const int lane = gid & 31;
    if (node >= N_NODES) return;

    const int d = g_cursor[node];
    const float dv = rsqrtf((float)d + 1.0f);
    if (lane == 0) g_dinv[node] = dv;

    uint2* p = (uint2*)(g_xwh + (size_t)node * OUT_C) + lane;
    uint2 u = *p;
    float2 f0 = __half22float2(*(const __half2*)&u.x);
    float2 f1 = __half22float2(*(const __half2*)&u.y);
    __half2 h0 = __floats2half2_rn(f0.x * dv, f0.y * dv);
    __half2 h1 = __floats2half2_rn(f1.x * dv, f1.y * dv);
    u.x = h2_to_u32(h0);
    u.y = h2_to_u32(h1);
    *p = u;
}

// ------------------------------------------------------------------
// gather: one warp per 2 nodes, batches of 4 neighbors from each interleaved
// (two independent dependency chains per iteration; same in-flight load count).
#define ACCUM_TO(u, AX, AY, AZ, AW) { \
    float2 f0 = __half22float2(*(const __half2*)&(u).x); \
    float2 f1 = __half22float2(*(const __half2*)&(u).y); \
    AX += f0.x; AY += f0.y; AZ += f1.x; AW += f1.y; }

__global__ void k_gather(const float* __restrict__ b, float* __restrict__ y) {
    const int pair = (blockIdx.x * blockDim.x + threadIdx.x) >> 5;
    const int lane = threadIdx.x & 31;
    const int n0 = pair * 2;
    const int n1 = n0 + 1;
    if (n0 >= N_NODES) return;

    int len0 = g_cursor[n0]; if (len0 > CAP) len0 = CAP;
    int len1 = (n1 < N_NODES) ? g_cursor[n1] : 0; if (len1 > CAP) len1 = CAP;
    int j0 = n0 * CAP, e0 = j0 + len0;
    int j1 = n1 * CAP, e1 = j1 + len1;

    float ax0 = 0.f, ay0 = 0.f, az0 = 0.f, aw0 = 0.f;
    float ax1 = 0.f, ay1 = 0.f, az1 = 0.f, aw1 = 0.f;

    // joint loop: 4 neighbors from each node per iteration
    while (j0 + 4 <= e0 && j1 + 4 <= e1) {
        int a0 = g_col[j0 + 0], a1 = g_col[j0 + 1], a2 = g_col[j0 + 2], a3 = g_col[j0 + 3];
        int b0 = g_col[j1 + 0], b1 = g_col[j1 + 1], b2 = g_col[j1 + 2], b3 = g_col[j1 + 3];
        uint2 ua0 = ((const uint2*)(g_xwh + (size_t)a0 * OUT_C))[lane];
        uint2 ub0 = ((const uint2*)(g_xwh + (size_t)b0 * OUT_C))[lane];
        uint2 ua1 = ((const uint2*)(g_xwh + (size_t)a1 * OUT_C))[lane];
        uint2 ub1 = ((const uint2*)(g_xwh + (size_t)b1 * OUT_C))[lane];
        uint2 ua2 = ((const uint2*)(g_xwh + (size_t)a2 * OUT_C))[lane];
        uint2 ub2 = ((const uint2*)(g_xwh + (size_t)b2 * OUT_C))[lane];
        uint2 ua3 = ((const uint2*)(g_xwh + (size_t)a3 * OUT_C))[lane];
        uint2 ub3 = ((const uint2*)(g_xwh + (size_t)b3 * OUT_C))[lane];
        ACCUM_TO(ua0, ax0, ay0, az0, aw0)
        ACCUM_TO(ub0, ax1, ay1, az1, aw1)
        ACCUM_TO(ua1, ax0, ay0, az0, aw0)
        ACCUM_TO(ub1, ax1, ay1, az1, aw1)
        ACCUM_TO(ua2, ax0, ay0, az0, aw0)
        ACCUM_TO(ub2, ax1, ay1, az1, aw1)
        ACCUM_TO(ua3, ax0, ay0, az0, aw0)
        ACCUM_TO(ub3, ax1, ay1, az1, aw1)
        j0 += 4; j1 += 4;
    }

    // node0 cleanup: batches of 8, then singles
    for (; j0 + 8 <= e0; j0 += 8) {
        int c0 = g_col[j0 + 0], c1 = g_col[j0 + 1], c2 = g_col[j0 + 2], c3 = g_col[j0 + 3];
        int c4 = g_col[j0 + 4], c5 = g_col[j0 + 5], c6 = g_col[j0 + 6], c7 = g_col[j0 + 7];
        uint2 u0 = ((const uint2*)(g_xwh + (size_t)c0 * OUT_C))[lane];
        uint2 u1 = ((const uint2*)(g_xwh + (size_t)c1 * OUT_C))[lane];
        uint2 u2 = ((const uint2*)(g_xwh + (size_t)c2 * OUT_C))[lane];
        uint2 u3 = ((const uint2*)(g_xwh + (size_t)c3 * OUT_C))[lane];
        uint2 u4 = ((const uint2*)(g_xwh + (size_t)c4 * OUT_C))[lane];
        uint2 u5 = ((const uint2*)(g_xwh + (size_t)c5 * OUT_C))[lane];
        uint2 u6 = ((const uint2*)(g_xwh + (size_t)c6 * OUT_C))[lane];
        uint2 u7 = ((const uint2*)(g_xwh + (size_t)c7 * OUT_C))[lane];
        ACCUM_TO(u0, ax0, ay0, az0, aw0) ACCUM_TO(u1, ax0, ay0, az0, aw0)
        ACCUM_TO(u2, ax0, ay0, az0, aw0) ACCUM_TO(u3, ax0, ay0, az0, aw0)
        ACCUM_TO(u4, ax0, ay0, az0, aw0) ACCUM_TO(u5, ax0, ay0, az0, aw0)
        ACCUM_TO(u6, ax0, ay0, az0, aw0) ACCUM_TO(u7, ax0, ay0, az0, aw0)
    }
    for (; j0 < e0; j0++) {
        int c = g_col[j0];
        uint2 u = ((const uint2*)(g_xwh + (size_t)c * OUT_C))[lane];
        ACCUM_TO(u, ax0, ay0, az0, aw0)
    }

    // node1 cleanup
    for (; j1 + 8 <= e1; j1 += 8) {
        int c0 = g_col[j1 + 0], c1 = g_col[j1 + 1], c2 = g_col[j1 + 2], c3 = g_col[j1 + 3];
        int c4 = g_col[j1 + 4], c5 = g_col[j1 + 5], c6 = g_col[j1 + 6], c7 = g_col[j1 + 7];
        uint2 u0 = ((const uint2*)(g_xwh + (size_t)c0 * OUT_C))[lane];
        uint2 u1 = ((const uint2*)(g_xwh + (size_t)c1 * OUT_C))[lane];
        uint2 u2 = ((const uint2*)(g_xwh + (size_t)c2 * OUT_C))[lane];
        uint2 u3 = ((const uint2*)(g_xwh + (size_t)c3 * OUT_C))[lane];
        uint2 u4 = ((const uint2*)(g_xwh + (size_t)c4 * OUT_C))[lane];
        uint2 u5 = ((const uint2*)(g_xwh + (size_t)c5 * OUT_C))[lane];
        uint2 u6 = ((const uint2*)(g_xwh + (size_t)c6 * OUT_C))[lane];
        uint2 u7 = ((const uint2*)(g_xwh + (size_t)c7 * OUT_C))[lane];
        ACCUM_TO(u0, ax1, ay1, az1, aw1) ACCUM_TO(u1, ax1, ay1, az1, aw1)
        ACCUM_TO(u2, ax1, ay1, az1, aw1) ACCUM_TO(u3, ax1, ay1, az1, aw1)
        ACCUM_TO(u4, ax1, ay1, az1, aw1) ACCUM_TO(u5, ax1, ay1, az1, aw1)
        ACCUM_TO(u6, ax1, ay1, az1, aw1) ACCUM_TO(u7, ax1, ay1, az1, aw1)
    }
    for (; j1 < e1; j1++) {
        int c = g_col[j1];
        uint2 u = ((const uint2*)(g_xwh + (size_t)c * OUT_C))[lane];
        ACCUM_TO(u, ax1, ay1, az1, aw1)
    }

    const float4 bv = ((const float4*)b)[lane];

    // node0 epilogue: self-loop + bias
    {
        uint2 u = ((const uint2*)(g_xwh + (size_t)n0 * OUT_C))[lane];
        ACCUM_TO(u, ax0, ay0, az0, aw0)
        const float dn = g_dinv[n0];
        float4 o;
        o.x = dn * ax0 + bv.x;
        o.y = dn * ay0 + bv.y;
        o.z = dn * az0 + bv.z;
        o.w = dn * aw0 + bv.w;
        ((float4*)(y + (size_t)n0 * OUT_C))[lane] = o;
    }
    // node1 epilogue
    if (n1 < N_NODES) {
        uint2 u = ((const uint2*)(g_xwh + (size_t)n1 * OUT_C))[lane];
        ACCUM_TO(u, ax1, ay1, az1, aw1)
        const float dn = g_dinv[n1];
        float4 o;
        o.x = dn * ax1 + bv.x;
        o.y = dn * ay1 + bv.y;
        o.z = dn * az1 + bv.z;
        o.w = dn * aw1 + bv.w;
        ((float4*)(y + (size_t)n1 * OUT_C))[lane] = o;
    }
}

// ------------------------------------------------------------------
extern "C" void kernel_launch(void* const* d_in, const int* in_sizes, int n_in,
                              void* d_out, int out_size) {
    const float* x  = (const float*)d_in[0];
    const float* W  = (const float*)d_in[1];
    const float* b  = (const float*)d_in[2];
    const int*   ei = (const int*)d_in[3];
    float* y = (float*)d_out;

    // zero bucket cursors via async memset (graph-capturable, no kernel)
    void* cur_ptr = nullptr;
    cudaGetSymbolAddress(&cur_ptr, g_cursor);
    cudaMemsetAsync(cur_ptr, 0, N_NODES * sizeof(int));

    // fused tensor-core GEMM (2 tiles/block) + one-pass bucketed fill
    k_gemm_fill<<<FUSED_BLOCKS, 256>>>(x, W, ei);

    // dinv + in-place fp16 prescale
    k_scale<<<(N_NODES * 32 + 255) / 256, 256>>>();

    // fused gather + self-loop + bias: one warp per 2 nodes
    const int pairs = (N_NODES + 1) / 2;                 // 50000
    const int gather_blocks = (pairs * 32 + 255) / 256;  // 6250
    k_gather<<<gather_blocks, 256>>>(b, y);
}